// round 6
// baseline (speedup 1.0000x reference)
#include <cuda_runtime.h>
#include <cstdint>

// DetectionCriterion: B=32, T=25, H=W=128.
//   output:         [32, 125, 128, 128] f32  (ch 0..24 = cls, 25..124 = reg, reg ch = 25 + j*25 + t)
//   class_map:      [32,  25, 128, 128] i32  in {0,1,2}  -> cm = v-1 in {-1,0,1}
//   regression_map: [32, 100, 128, 128] f32  (ch = j*25 + t)
//   noise:          [32,  25, 128, 128] f32  uniform [0,1)
// Result: sum of masked softplus cls loss over sampled elements (<=128 pos + <=128 neg
// per batch row, smallest-noise-first among mined candidates, ties-at-threshold kept)
// plus 2.0 * smooth_l1 reg loss over kept positives x 4 channels.
//
// State invariant: all __device__ globals are zero at module load; every call
// leaves them zero again (pass2 resets g_cnt[bc] after consuming it; the last
// pass2 block resets g_done after the final reduction). This makes the 2-launch
// sequence deterministic under graph capture + replay with no zeroing kernel.

#define NB 32
#define ELEMS_PER_B (25 * 128 * 128)      // 409600
#define OUT_STRIDE_B (125 * 16384)        // 2048000
#define REG_STRIDE_B (100 * 16384)        // 1638400
#define CAP 16384                         // stash capacity per (b, class)
#define STAGE_CAP 1024                    // per-block shared staging per class
#define K_SAMPLE 128
// drop if softplus(-cls*cm) < 0.03  <=>  -cls*cm < ln(e^0.03 - 1)
#define MINING_CUT (-3.4915206f)
// stash everything with noise < 1/32 (bits < 0x3D000000). The 128th-smallest
// noise among ~136K uniform candidates is ~9.4e-4, 33x below this cut.
#define STASH_BITS 0x3D000000u

__device__ int      g_cnt[NB * 2];        // zero-init at load; restored to 0 each call
__device__ unsigned g_key[NB * 2 * CAP];
__device__ unsigned g_idx[NB * 2 * CAP];
__device__ float    g_cls[NB * 2 * CAP];
__device__ double   g_partial[NB * 2];
__device__ int      g_done;               // zero-init at load; restored to 0 each call

// Pass 1: scan class_map + cls + noise; stash candidates with small noise.
// Grid: (25, 32), 256 threads, 16384 elements per block via float4/int4 loads.
__global__ __launch_bounds__(256) void pass1_kernel(
    const float* __restrict__ out,
    const int* __restrict__ cmap,
    const float* __restrict__ noise)
{
    const int b = blockIdx.y;
    const int tid = threadIdx.x;

    __shared__ int      s_cnt[2];
    __shared__ int      s_base[2];
    __shared__ unsigned s_key[2][STAGE_CAP];
    __shared__ unsigned s_idx[2][STAGE_CAP];
    __shared__ float    s_cls[2][STAGE_CAP];

    if (tid < 2) s_cnt[tid] = 0;
    __syncthreads();

    const int base = blockIdx.x * 16384;
    const int4*   cm4 = (const int4*)  (cmap  + (size_t)b * ELEMS_PER_B + base);
    const float4* cl4 = (const float4*)(out   + (size_t)b * OUT_STRIDE_B + base);
    const float4* nz4 = (const float4*)(noise + (size_t)b * ELEMS_PER_B + base);

    // 16 iterations x 3 vec loads: keep MLP high so the 577-cyc DRAM latency is
    // covered by outstanding LDG.128s (B300: ~55 outstanding LDG per warp OK).
    #pragma unroll 8
    for (int it = 0; it < 16; ++it) {
        const int v = it * 256 + tid;
        const int4   cm = __ldg(&cm4[v]);
        const float4 cl = __ldg(&cl4[v]);
        const float4 nz = __ldg(&nz4[v]);

        const int   cma[4] = {cm.x - 1, cm.y - 1, cm.z - 1, cm.w - 1};
        const float cla[4] = {cl.x, cl.y, cl.z, cl.w};
        const float nza[4] = {nz.x, nz.y, nz.z, nz.w};

        #pragma unroll
        for (int j = 0; j < 4; ++j) {
            const int cmv = cma[j];
            if (cmv == 0) continue;
            const float cls = cla[j];
            const float z = -cls * (float)cmv;
            if (z < MINING_CUT) continue;                 // mined out (easy example)
            const unsigned bits = __float_as_uint(nza[j]);
            if (bits >= STASH_BITS) continue;             // cannot be in top-128 smallest
            const int c = (cmv == 1) ? 0 : 1;
            const unsigned idx = (unsigned)(base + v * 4 + j);
            const int slot = atomicAdd(&s_cnt[c], 1);
            if (slot < STAGE_CAP) {
                s_key[c][slot] = bits; s_idx[c][slot] = idx; s_cls[c][slot] = cls;
            } else {  // staging overflow (statistically never): spill direct
                const int g = atomicAdd(&g_cnt[b * 2 + c], 1);
                if (g < CAP) {
                    const size_t o = (size_t)(b * 2 + c) * CAP + g;
                    g_key[o] = bits; g_idx[o] = idx; g_cls[o] = cls;
                }
            }
        }
    }
    __syncthreads();

    if (tid < 2) {
        int m = s_cnt[tid]; if (m > STAGE_CAP) m = STAGE_CAP;
        s_base[tid] = atomicAdd(&g_cnt[b * 2 + tid], m);
    }
    __syncthreads();

    #pragma unroll
    for (int c = 0; c < 2; ++c) {
        int m = s_cnt[c]; if (m > STAGE_CAP) m = STAGE_CAP;
        for (int i = tid; i < m; i += 256) {
            const int g = s_base[c] + i;
            if (g < CAP) {
                const size_t o = (size_t)(b * 2 + c) * CAP + g;
                g_key[o] = s_key[c][i]; g_idx[o] = s_idx[c][i]; g_cls[o] = s_cls[c][i];
            }
        }
    }
}

// Pass 2: one block per (b, class). Exact k-th smallest noise via 512-bin radix
// histogram over float bit patterns (order-preserving for non-negative floats),
// then accumulate cls loss over kept entries and gathered reg loss for positives.
// The last block to finish folds g_partial[64] into the final scalar (saves a launch).
__global__ __launch_bounds__(256) void pass2_kernel(
    const float* __restrict__ out,
    const float* __restrict__ rmap,
    float* __restrict__ outp)
{
    const int bc = blockIdx.x;
    const int b = bc >> 1, c = bc & 1;
    const int tid = threadIdx.x;

    __shared__ int      s_hist[512];
    __shared__ unsigned s_bk[1024];
    __shared__ int      s_m, s_B, s_r;
    __shared__ unsigned s_t;
    __shared__ double   s_red[256];
    __shared__ bool     s_last;

    for (int i = tid; i < 512; i += 256) s_hist[i] = 0;
    if (tid == 0) s_m = 0;
    __syncthreads();

    int n = g_cnt[bc]; if (n > CAP) n = CAP;
    if (tid == 0) g_cnt[bc] = 0;      // restore invariant for next graph replay
    const unsigned* __restrict__ keys = g_key + (size_t)bc * CAP;

    for (int i = tid; i < n; i += 256) atomicAdd(&s_hist[keys[i] >> 21], 1);
    __syncthreads();

    if (tid == 0) {
        int cum = 0, B = -1, r = 0;
        for (int i = 0; i < 512; ++i) {
            const int h = s_hist[i];
            if (cum + h >= K_SAMPLE) { B = i; r = K_SAMPLE - cum; break; }
            cum += h;
        }
        s_B = B; s_r = r;
    }
    __syncthreads();

    unsigned t;
    if (s_B < 0) {
        t = 0xFFFFFFFFu;    // fewer than 128 candidates: keep all stashed
    } else {
        const int B = s_B;
        for (int i = tid; i < n; i += 256) {
            const unsigned kk = keys[i];
            if ((int)(kk >> 21) == B) {
                const int p = atomicAdd(&s_m, 1);
                if (p < 1024) s_bk[p] = kk;
            }
        }
        __syncthreads();
        if (tid == 0) {
            int m = s_m; if (m > 1024) m = 1024;
            const int r = s_r;
            unsigned tt = 0xFFFFFFFFu;
            for (int q = 0; q < r; ++q) {          // r-th smallest within boundary bin
                unsigned mn = 0xFFFFFFFFu; int mi = 0;
                for (int j = 0; j < m; ++j) {
                    const unsigned vv = s_bk[j];
                    if (vv < mn) { mn = vv; mi = j; }
                }
                tt = mn; s_bk[mi] = 0xFFFFFFFFu;
            }
            s_t = tt;
        }
        __syncthreads();
        t = s_t;
    }

    double lsum = 0.0;
    const float sgn = (c == 0) ? 1.0f : -1.0f;
    const unsigned* __restrict__ gi = g_idx + (size_t)bc * CAP;
    const float*    __restrict__ gc = g_cls + (size_t)bc * CAP;
    const float* outb = out  + (size_t)b * OUT_STRIDE_B;
    const float* rmb  = rmap + (size_t)b * REG_STRIDE_B;

    for (int i = tid; i < n; i += 256) {
        const unsigned kk = keys[i];
        if (kk <= t) {                               // noise <= thresh (ties kept)
            const float cls = gc[i];
            const float z = -cls * sgn;
            lsum += (double)log1pf(expf(z));         // softplus cls loss
            if (c == 0) {                            // kept positive: reg loss
                const unsigned idx = gi[i];
                const int tmpl = idx >> 14;
                const int hw = idx & 16383;
                const float* rp = outb + (25 + tmpl) * 16384 + hw;
                const float* gp = rmb  + tmpl * 16384 + hw;
                #pragma unroll
                for (int j = 0; j < 4; ++j) {
                    const float d = __ldg(&rp[j * ELEMS_PER_B]) - __ldg(&gp[j * ELEMS_PER_B]);
                    const float ad = fabsf(d);
                    const float sl = (ad < 1.0f) ? 0.5f * d * d : ad - 0.5f;
                    lsum += 2.0 * (double)sl;        // REG_WEIGHT = 2.0
                }
            }
        }
    }

    s_red[tid] = lsum;
    __syncthreads();
    for (int s = 128; s > 0; s >>= 1) {
        if (tid < s) s_red[tid] += s_red[tid + s];
        __syncthreads();
    }
    if (tid == 0) {
        g_partial[bc] = s_red[0];
        __threadfence();                              // publish before signaling done
        s_last = (atomicAdd(&g_done, 1) == NB * 2 - 1);
    }
    __syncthreads();

    // Last-finishing block performs the final 64-way reduction (fixed order,
    // deterministic) and restores g_done = 0 for the next replay.
    if (s_last) {
        double v = (tid < NB * 2) ? g_partial[tid] : 0.0;
        s_red[tid] = v;
        __syncthreads();
        for (int s = 32; s > 0; s >>= 1) {
            if (tid < s) s_red[tid] += s_red[tid + s];
            __syncthreads();
        }
        if (tid == 0) {
            outp[0] = (float)s_red[0];
            g_done = 0;                               // restore invariant
        }
    }
}

extern "C" void kernel_launch(void* const* d_in, const int* in_sizes, int n_in,
                              void* d_out, int out_size) {
    const float* output = (const float*)d_in[0];
    const int*   cmap   = (const int*)  d_in[1];
    const float* rmap   = (const float*)d_in[2];
    const float* noise  = (const float*)d_in[3];
    float* outp = (float*)d_out;

    dim3 g1(25, 32);
    pass1_kernel<<<g1, 256>>>(output, cmap, noise);
    pass2_kernel<<<64, 256>>>(output, rmap, outp);
}

// round 8
// speedup vs baseline: 1.8154x; 1.8154x over previous
#include <cuda_runtime.h>
#include <cstdint>

// DetectionCriterion: B=32, T=25, H=W=128.
//   output:         [32, 125, 128, 128] f32  (ch 0..24 = cls, 25..124 = reg, reg ch = 25 + j*25 + t)
//   class_map:      [32,  25, 128, 128] i32  in {0,1,2}  -> cm = v-1 in {-1,0,1}
//   regression_map: [32, 100, 128, 128] f32  (ch = j*25 + t)
//   noise:          [32,  25, 128, 128] f32  uniform [0,1)
//
// R6 redesign of pass2: stash cut tightened 1/32 -> 1/512 (n: ~4266 -> ~267 per
// (b,class); the 128th-smallest noise ~9.4e-4 is 12 sigma below the 1.95e-3 cut,
// so exactness holds). Serial histogram/boundary-bin select replaced by a fully
// parallel O(n^2/256) strict-rank selection in shared memory.
//
// State invariant: all __device__ globals are zero at module load; every call
// restores them to zero (pass2 resets g_cnt[bc]; last pass2 block resets g_done).

#define NB 32
#define ELEMS_PER_B (25 * 128 * 128)      // 409600
#define OUT_STRIDE_B (125 * 16384)        // 2048000
#define REG_STRIDE_B (100 * 16384)        // 1638400
#define CAP 1024                          // stash capacity per (b, class); mean ~267
#define STAGE_CAP 128                     // per-block shared staging per class; mean ~11
#define K_SAMPLE 128
// drop if softplus(-cls*cm) < 0.03  <=>  -cls*cm < ln(e^0.03 - 1)
#define MINING_CUT (-3.4915206f)
// stash everything with noise < 1/512 (bits < 0x3B000000). The 128th-smallest
// noise among ~136K uniform candidates is ~9.4e-4 (sigma 8.3e-5), 12 sigma
// below this cut -> exact with astronomically high probability.
#define STASH_BITS 0x3B000000u

__device__ int      g_cnt[NB * 2];        // zero at load; restored each call
__device__ unsigned g_key[NB * 2 * CAP];
__device__ unsigned g_idx[NB * 2 * CAP];
__device__ float    g_cls[NB * 2 * CAP];
__device__ double   g_partial[NB * 2];
__device__ int      g_done;               // zero at load; restored each call

// Pass 1: scan class_map + cls + noise; stash candidates with small noise.
// Grid: (25, 32), 256 threads, 16384 elements per block via float4/int4 loads.
__global__ __launch_bounds__(256) void pass1_kernel(
    const float* __restrict__ out,
    const int* __restrict__ cmap,
    const float* __restrict__ noise)
{
    const int b = blockIdx.y;
    const int tid = threadIdx.x;

    __shared__ int      s_cnt[2];
    __shared__ int      s_base[2];
    __shared__ unsigned s_key[2][STAGE_CAP];
    __shared__ unsigned s_idx[2][STAGE_CAP];
    __shared__ float    s_cls[2][STAGE_CAP];

    if (tid < 2) s_cnt[tid] = 0;
    __syncthreads();

    const int base = blockIdx.x * 16384;
    const int4*   cm4 = (const int4*)  (cmap  + (size_t)b * ELEMS_PER_B + base);
    const float4* cl4 = (const float4*)(out   + (size_t)b * OUT_STRIDE_B + base);
    const float4* nz4 = (const float4*)(noise + (size_t)b * ELEMS_PER_B + base);

    // 16 iterations x 3 vec loads: keep MLP high so the ~577-cyc DRAM latency is
    // covered by outstanding LDG.128s.
    #pragma unroll 8
    for (int it = 0; it < 16; ++it) {
        const int v = it * 256 + tid;
        const int4   cm = __ldg(&cm4[v]);
        const float4 cl = __ldg(&cl4[v]);
        const float4 nz = __ldg(&nz4[v]);

        const int   cma[4] = {cm.x - 1, cm.y - 1, cm.z - 1, cm.w - 1};
        const float cla[4] = {cl.x, cl.y, cl.z, cl.w};
        const float nza[4] = {nz.x, nz.y, nz.z, nz.w};

        #pragma unroll
        for (int j = 0; j < 4; ++j) {
            const int cmv = cma[j];
            if (cmv == 0) continue;
            const float cls = cla[j];
            const float z = -cls * (float)cmv;
            if (z < MINING_CUT) continue;                 // mined out (easy example)
            const unsigned bits = __float_as_uint(nza[j]);
            if (bits >= STASH_BITS) continue;             // cannot be in top-128 smallest
            const int c = (cmv == 1) ? 0 : 1;
            const unsigned idx = (unsigned)(base + v * 4 + j);
            const int slot = atomicAdd(&s_cnt[c], 1);
            if (slot < STAGE_CAP) {
                s_key[c][slot] = bits; s_idx[c][slot] = idx; s_cls[c][slot] = cls;
            } else {  // staging overflow (statistically never): spill direct
                const int g = atomicAdd(&g_cnt[b * 2 + c], 1);
                if (g < CAP) {
                    const size_t o = (size_t)(b * 2 + c) * CAP + g;
                    g_key[o] = bits; g_idx[o] = idx; g_cls[o] = cls;
                }
            }
        }
    }
    __syncthreads();

    if (tid < 2) {
        int m = s_cnt[tid]; if (m > STAGE_CAP) m = STAGE_CAP;
        s_base[tid] = atomicAdd(&g_cnt[b * 2 + tid], m);
    }
    __syncthreads();

    #pragma unroll
    for (int c = 0; c < 2; ++c) {
        int m = s_cnt[c]; if (m > STAGE_CAP) m = STAGE_CAP;
        for (int i = tid; i < m; i += 256) {
            const int g = s_base[c] + i;
            if (g < CAP) {
                const size_t o = (size_t)(b * 2 + c) * CAP + g;
                g_key[o] = s_key[c][i]; g_idx[o] = s_idx[c][i]; g_cls[o] = s_cls[c][i];
            }
        }
    }
}

// Pass 2: one block per (b, class). Parallel exact selection: for each stashed
// key compute its strict rank (count of smaller keys) over shared memory; the
// threshold t = max{key : strict_rank < K} is exactly the K-th smallest value
// (and max-of-all when n <= K, reproducing the reference keep-all branch).
// Keep kk <= t (ties at threshold kept, matching `scores <= thresh`).
// Last-finishing block folds g_partial[64] into the final scalar.
__global__ __launch_bounds__(256) void pass2_kernel(
    const float* __restrict__ out,
    const float* __restrict__ rmap,
    float* __restrict__ outp)
{
    const int bc = blockIdx.x;
    const int b = bc >> 1, c = bc & 1;
    const int tid = threadIdx.x;

    __shared__ unsigned s_keys[CAP];
    __shared__ unsigned s_ru[256];
    __shared__ double   s_red[256];
    __shared__ bool     s_last;

    int n = g_cnt[bc]; if (n > CAP) n = CAP;
    if (tid == 0) g_cnt[bc] = 0;      // restore invariant for next graph replay

    const unsigned* __restrict__ keys = g_key + (size_t)bc * CAP;
    for (int i = tid; i < n; i += 256) s_keys[i] = keys[i];
    __syncthreads();

    // Parallel strict-rank selection (~n^2/256 broadcast-LDS compares total).
    unsigned tloc = 0;
    for (int i = tid; i < n; i += 256) {
        const unsigned kk = s_keys[i];
        int ls = 0;
        for (int j = 0; j < n; ++j) ls += (s_keys[j] < kk) ? 1 : 0;
        if (ls < K_SAMPLE && kk > tloc) tloc = kk;
    }
    s_ru[tid] = tloc;
    __syncthreads();
    for (int s = 128; s > 0; s >>= 1) {
        if (tid < s) { const unsigned o = s_ru[tid + s]; if (o > s_ru[tid]) s_ru[tid] = o; }
        __syncthreads();
    }
    const unsigned t = s_ru[0];

    double lsum = 0.0;
    const float sgn = (c == 0) ? 1.0f : -1.0f;
    const unsigned* __restrict__ gi = g_idx + (size_t)bc * CAP;
    const float*    __restrict__ gc = g_cls + (size_t)bc * CAP;
    const float* outb = out  + (size_t)b * OUT_STRIDE_B;
    const float* rmb  = rmap + (size_t)b * REG_STRIDE_B;

    for (int i = tid; i < n; i += 256) {
        const unsigned kk = s_keys[i];
        if (kk <= t) {                               // noise <= thresh (ties kept)
            const float cls = gc[i];
            const float z = -cls * sgn;
            lsum += (double)log1pf(expf(z));         // softplus cls loss
            if (c == 0) {                            // kept positive: reg loss
                const unsigned idx = gi[i];
                const int tmpl = idx >> 14;
                const int hw = idx & 16383;
                const float* rp = outb + (25 + tmpl) * 16384 + hw;
                const float* gp = rmb  + tmpl * 16384 + hw;
                #pragma unroll
                for (int j = 0; j < 4; ++j) {
                    const float d = __ldg(&rp[j * ELEMS_PER_B]) - __ldg(&gp[j * ELEMS_PER_B]);
                    const float ad = fabsf(d);
                    const float sl = (ad < 1.0f) ? 0.5f * d * d : ad - 0.5f;
                    lsum += 2.0 * (double)sl;        // REG_WEIGHT = 2.0
                }
            }
        }
    }

    s_red[tid] = lsum;
    __syncthreads();
    for (int s = 128; s > 0; s >>= 1) {
        if (tid < s) s_red[tid] += s_red[tid + s];
        __syncthreads();
    }
    if (tid == 0) {
        g_partial[bc] = s_red[0];
        __threadfence();                              // publish before signaling done
        s_last = (atomicAdd(&g_done, 1) == NB * 2 - 1);
    }
    __syncthreads();

    // Last-finishing block: final 64-way reduction (fixed order, deterministic),
    // then restore g_done = 0 for the next replay.
    if (s_last) {
        double v = (tid < NB * 2) ? g_partial[tid] : 0.0;
        s_red[tid] = v;
        __syncthreads();
        for (int s = 32; s > 0; s >>= 1) {
            if (tid < s) s_red[tid] += s_red[tid + s];
            __syncthreads();
        }
        if (tid == 0) {
            outp[0] = (float)s_red[0];
            g_done = 0;                               // restore invariant
        }
    }
}

extern "C" void kernel_launch(void* const* d_in, const int* in_sizes, int n_in,
                              void* d_out, int out_size) {
    const float* output = (const float*)d_in[0];
    const int*   cmap   = (const int*)  d_in[1];
    const float* rmap   = (const float*)d_in[2];
    const float* noise  = (const float*)d_in[3];
    float* outp = (float*)d_out;

    dim3 g1(25, 32);
    pass1_kernel<<<g1, 256>>>(output, cmap, noise);
    pass2_kernel<<<64, 256>>>(output, rmap, outp);
}

// round 13
// speedup vs baseline: 2.0858x; 1.1490x over previous
#include <cuda_runtime.h>
#include <cstdint>

// DetectionCriterion: B=32, T=25, H=W=128.
//   output:         [32, 125, 128, 128] f32  (ch 0..24 = cls, 25..124 = reg, reg ch = 25 + j*25 + t)
//   class_map:      [32,  25, 128, 128] i32  in {0,1,2}  -> cm = v-1 in {-1,0,1}
//   regression_map: [32, 100, 128, 128] f32  (ch = j*25 + t)
//   noise:          [32,  25, 128, 128] f32  uniform [0,1)
//
// pass2: 512 threads, one candidate per thread in registers; unconditional
// parallel loads (masked by n afterwards) to break the g_cnt -> keys chain;
// speculative reg-gather prefetch issued before the rank phase (addresses from
// g_idx are always in-bounds: pass1 writes only idx < 409600, zero-init else);
// 4-accumulator ILP rank scan; shuffle reductions. Selection exact:
// t = max{key : strict_rank < 128} = 128th order statistic; kk <= t keeps ties.
//
// State invariant: all __device__ globals are zero at module load; every call
// restores them to zero (pass2 resets g_cnt[bc]; last pass2 block resets g_done).

#define NB 32
#define ELEMS_PER_B (25 * 128 * 128)      // 409600
#define OUT_STRIDE_B (125 * 16384)        // 2048000
#define REG_STRIDE_B (100 * 16384)        // 1638400
#define CAP 1024                          // stash capacity per (b, class); mean ~267
#define STAGE_CAP 128                     // per-block shared staging per class; mean ~11
#define K_SAMPLE 128
#define P2_THREADS 512
// drop if softplus(-cls*cm) < 0.03  <=>  -cls*cm < ln(e^0.03 - 1)
#define MINING_CUT (-3.4915206f)
// stash everything with noise < 1/512 (bits < 0x3B000000). The 128th-smallest
// noise among ~136K uniform candidates is ~9.4e-4 (sigma 8.3e-5), 12 sigma
// below this cut -> exact with astronomically high probability.
#define STASH_BITS 0x3B000000u

__device__ int      g_cnt[NB * 2];        // zero at load; restored each call
__device__ unsigned g_key[NB * 2 * CAP];
__device__ unsigned g_idx[NB * 2 * CAP];
__device__ float    g_cls[NB * 2 * CAP];
__device__ double   g_partial[NB * 2];
__device__ int      g_done;               // zero at load; restored each call

// Pass 1: scan class_map + cls + noise; stash candidates with small noise.
// Grid: (25, 32), 256 threads, 16384 elements per block via float4/int4 loads.
__global__ __launch_bounds__(256) void pass1_kernel(
    const float* __restrict__ out,
    const int* __restrict__ cmap,
    const float* __restrict__ noise)
{
    const int b = blockIdx.y;
    const int tid = threadIdx.x;

    __shared__ int      s_cnt[2];
    __shared__ int      s_base[2];
    __shared__ unsigned s_key[2][STAGE_CAP];
    __shared__ unsigned s_idx[2][STAGE_CAP];
    __shared__ float    s_cls[2][STAGE_CAP];

    if (tid < 2) s_cnt[tid] = 0;
    __syncthreads();

    const int base = blockIdx.x * 16384;
    const int4*   cm4 = (const int4*)  (cmap  + (size_t)b * ELEMS_PER_B + base);
    const float4* cl4 = (const float4*)(out   + (size_t)b * OUT_STRIDE_B + base);
    const float4* nz4 = (const float4*)(noise + (size_t)b * ELEMS_PER_B + base);

    #pragma unroll 8
    for (int it = 0; it < 16; ++it) {
        const int v = it * 256 + tid;
        const int4   cm = __ldg(&cm4[v]);
        const float4 cl = __ldg(&cl4[v]);
        const float4 nz = __ldg(&nz4[v]);

        const int   cma[4] = {cm.x - 1, cm.y - 1, cm.z - 1, cm.w - 1};
        const float cla[4] = {cl.x, cl.y, cl.z, cl.w};
        const float nza[4] = {nz.x, nz.y, nz.z, nz.w};

        #pragma unroll
        for (int j = 0; j < 4; ++j) {
            const int cmv = cma[j];
            if (cmv == 0) continue;
            const float cls = cla[j];
            const float z = -cls * (float)cmv;
            if (z < MINING_CUT) continue;                 // mined out (easy example)
            const unsigned bits = __float_as_uint(nza[j]);
            if (bits >= STASH_BITS) continue;             // cannot be in top-128 smallest
            const int c = (cmv == 1) ? 0 : 1;
            const unsigned idx = (unsigned)(base + v * 4 + j);
            const int slot = atomicAdd(&s_cnt[c], 1);
            if (slot < STAGE_CAP) {
                s_key[c][slot] = bits; s_idx[c][slot] = idx; s_cls[c][slot] = cls;
            } else {  // staging overflow (statistically never): spill direct
                const int g = atomicAdd(&g_cnt[b * 2 + c], 1);
                if (g < CAP) {
                    const size_t o = (size_t)(b * 2 + c) * CAP + g;
                    g_key[o] = bits; g_idx[o] = idx; g_cls[o] = cls;
                }
            }
        }
    }
    __syncthreads();

    if (tid < 2) {
        int m = s_cnt[tid]; if (m > STAGE_CAP) m = STAGE_CAP;
        s_base[tid] = atomicAdd(&g_cnt[b * 2 + tid], m);
    }
    __syncthreads();

    #pragma unroll
    for (int c = 0; c < 2; ++c) {
        int m = s_cnt[c]; if (m > STAGE_CAP) m = STAGE_CAP;
        for (int i = tid; i < m; i += 256) {
            const int g = s_base[c] + i;
            if (g < CAP) {
                const size_t o = (size_t)(b * 2 + c) * CAP + g;
                g_key[o] = s_key[c][i]; g_idx[o] = s_idx[c][i]; g_cls[o] = s_cls[c][i];
            }
        }
    }
}

// Pass 2: one block of 512 threads per (b, class); one candidate per thread.
__global__ __launch_bounds__(P2_THREADS) void pass2_kernel(
    const float* __restrict__ out,
    const float* __restrict__ rmap,
    float* __restrict__ outp)
{
    const int bc = blockIdx.x;
    const int b = bc >> 1, c = bc & 1;
    const int tid = threadIdx.x;
    const int wid = tid >> 5, lane = tid & 31;

    __shared__ unsigned s_keys[P2_THREADS];
    __shared__ int      s_n;
    __shared__ unsigned s_mx[16];
    __shared__ double   s_red[16];
    __shared__ double   s_fin[64];
    __shared__ bool     s_last;

    // Issue all loads in parallel (no dependency on n; slots >= n masked below;
    // masked garbage cannot affect the output).
    const size_t rowo = (size_t)bc * CAP;
    const unsigned kraw = g_key[rowo + tid];
    const float    craw = g_cls[rowo + tid];
    const unsigned iraw = g_idx[rowo + tid];
    if (tid == 0) {
        int nn = g_cnt[bc];
        if (nn > P2_THREADS) nn = P2_THREADS;   // P(n > 512) ~ 15 sigma: never
        s_n = nn;
        g_cnt[bc] = 0;                          // restore invariant (after the read)
    }
    s_keys[tid] = kraw;

    // Speculative reg-gather prefetch (pos blocks only): addresses depend only
    // on iraw, which is always a valid pass1 index (< 409600 -> tmpl < 25) or
    // zero -> in-bounds. Overlaps the second DRAM round with the rank phase;
    // values are consumed only if this candidate is kept.
    float pf_r[4], pf_g[4];
    if (c == 0) {
        const int tmpl = iraw >> 14;
        const int hw = iraw & 16383;
        const float* rp = out  + (size_t)b * OUT_STRIDE_B + (25 + tmpl) * 16384 + hw;
        const float* gp = rmap + (size_t)b * REG_STRIDE_B + tmpl * 16384 + hw;
        #pragma unroll
        for (int q = 0; q < 4; ++q) {
            pf_r[q] = __ldg(&rp[q * ELEMS_PER_B]);
            pf_g[q] = __ldg(&gp[q * ELEMS_PER_B]);
        }
    }

    __syncthreads();
    const int n = s_n;
    const unsigned kk = (tid < n) ? kraw : 0xFFFFFFFFu;

    // Strict rank of kk among the n real keys: 4 independent accumulators so
    // LDS latency is pipelined instead of serialized.
    int l0 = 0, l1 = 0, l2 = 0, l3 = 0;
    int j = 0;
    #pragma unroll 2
    for (; j + 4 <= n; j += 4) {
        l0 += (s_keys[j]     < kk) ? 1 : 0;
        l1 += (s_keys[j + 1] < kk) ? 1 : 0;
        l2 += (s_keys[j + 2] < kk) ? 1 : 0;
        l3 += (s_keys[j + 3] < kk) ? 1 : 0;
    }
    for (; j < n; ++j) l0 += (s_keys[j] < kk) ? 1 : 0;
    const int ls = (l0 + l1) + (l2 + l3);

    // t = max{key : rank < K} over real keys = exact K-th smallest
    // (max of all keys when n <= K -> keep-all branch of the reference).
    unsigned tl = (tid < n && ls < K_SAMPLE) ? kk : 0u;
    tl = __reduce_max_sync(0xFFFFFFFFu, tl);
    if (lane == 0) s_mx[wid] = tl;
    __syncthreads();
    if (wid == 0) {
        unsigned v = (lane < 16) ? s_mx[lane] : 0u;
        v = __reduce_max_sync(0xFFFFFFFFu, v);
        if (lane == 0) s_mx[0] = v;
    }
    __syncthreads();
    const unsigned t = s_mx[0];

    // Loss for kept candidates (noise <= thresh, ties kept).
    double lsum = 0.0;
    if (tid < n && kk <= t) {
        const float sgn = (c == 0) ? 1.0f : -1.0f;
        const float z = -craw * sgn;
        lsum = (double)log1pf(expf(z));               // softplus cls loss
        if (c == 0) {                                 // kept positive: reg loss
            #pragma unroll
            for (int q = 0; q < 4; ++q) {
                const float d = pf_r[q] - pf_g[q];
                const float ad = fabsf(d);
                const float sl = (ad < 1.0f) ? 0.5f * d * d : ad - 0.5f;
                lsum += 2.0 * (double)sl;             // REG_WEIGHT = 2.0
            }
        }
    }

    // Block reduction: warp shuffles, then warp 0 over 16 partials.
    #pragma unroll
    for (int off = 16; off > 0; off >>= 1)
        lsum += __shfl_down_sync(0xFFFFFFFFu, lsum, off);
    if (lane == 0) s_red[wid] = lsum;
    __syncthreads();
    if (wid == 0) {
        double v = (lane < 16) ? s_red[lane] : 0.0;
        #pragma unroll
        for (int off = 8; off > 0; off >>= 1)
            v += __shfl_down_sync(0xFFFFFFFFu, v, off);
        if (lane == 0) {
            g_partial[bc] = v;
            __threadfence();                          // publish before signaling done
            s_last = (atomicAdd(&g_done, 1) == NB * 2 - 1);
        }
    }
    __syncthreads();

    // Last-finishing block: deterministic fixed-order 64-way final reduction,
    // then restore g_done = 0 for the next replay.
    if (s_last) {
        if (tid < 64) s_fin[tid] = g_partial[tid];
        __syncthreads();
        for (int s = 32; s > 0; s >>= 1) {
            if (tid < s) s_fin[tid] += s_fin[tid + s];
            __syncthreads();
        }
        if (tid == 0) {
            outp[0] = (float)s_fin[0];
            g_done = 0;                               // restore invariant
        }
    }
}

extern "C" void kernel_launch(void* const* d_in, const int* in_sizes, int n_in,
                              void* d_out, int out_size) {
    const float* output = (const float*)d_in[0];
    const int*   cmap   = (const int*)  d_in[1];
    const float* rmap   = (const float*)d_in[2];
    const float* noise  = (const float*)d_in[3];
    float* outp = (float*)d_out;

    dim3 g1(25, 32);
    pass1_kernel<<<g1, 256>>>(output, cmap, noise);
    pass2_kernel<<<64, P2_THREADS>>>(output, rmap, outp);
}